// round 6
// baseline (speedup 1.0000x reference)
#include <cuda_runtime.h>
#include <cuda_bf16.h>
#include <math.h>

// ---------------------------------------------------------------------------
// 2-layer LSTM, B=16, T=1024, D=H=512, fp32.
// Round 4: barrier-free scan — per-producer release/acquire tagged flags,
// 2-slot ping-pong h exchange, no threadfence, no global barrier.
// ---------------------------------------------------------------------------

#define Bsz   16
#define Tlen  1024
#define Hdim  512
#define G4H   2048
#define NBLK  128

__device__ float g_gx[(size_t)Bsz * Tlen * G4H];
__device__ float g_out0[(size_t)Bsz * Tlen * Hdim];
__device__ float g_hbuf[2][Bsz * Hdim];
__device__ unsigned int g_flag[2][NBLK * 8];   // [slot][cta*8], 32B stride
__device__ unsigned int g_epoch;               // monotonic tag base

union F4U2 { float4 f; ulonglong2 u; };

__device__ __forceinline__ unsigned long long ffma2(unsigned long long a,
                                                    unsigned long long b,
                                                    unsigned long long c) {
    unsigned long long d;
    asm("fma.rn.f32x2 %0, %1, %2, %3;" : "=l"(d) : "l"(a), "l"(b), "l"(c));
    return d;
}
__device__ __forceinline__ unsigned long long dup2(float x) {
    unsigned long long r;
    asm("mov.b64 %0, {%1, %1};" : "=l"(r) : "f"(x));
    return r;
}
__device__ __forceinline__ void unpk2(unsigned long long v, float& lo, float& hi) {
    asm("mov.b64 {%0, %1}, %2;" : "=f"(lo), "=f"(hi) : "l"(v));
}
__device__ __forceinline__ unsigned int ld_acq(const unsigned int* p) {
    unsigned int v;
    asm volatile("ld.acquire.gpu.global.u32 %0, [%1];" : "=r"(v) : "l"(p) : "memory");
    return v;
}
__device__ __forceinline__ void st_rel(unsigned int* p, unsigned int v) {
    asm volatile("st.release.gpu.global.u32 [%0], %1;" :: "l"(p), "r"(v) : "memory");
}

// ---------------------------------------------------------------------------
// GEMM (NT), unchanged.
// ---------------------------------------------------------------------------
#define GP 132

__global__ __launch_bounds__(256, 2) void gemm_nt_bias(
    const float* __restrict__ A, const float* __restrict__ B,
    const float* __restrict__ bias, float* __restrict__ C,
    int M, int N, int K)
{
    __shared__ float As[32][GP];
    __shared__ float Bs[32][GP];

    const int tid = threadIdx.x;
    const int m0 = blockIdx.y * 128;
    const int n0 = blockIdx.x * 128;
    const int tx = tid & 15;
    const int ty = tid >> 4;
    const int lrow = tid >> 3;
    const int lkq  = tid & 7;

    unsigned long long acc[8][4];
#pragma unroll
    for (int i = 0; i < 8; i++)
#pragma unroll
        for (int j = 0; j < 4; j++) acc[i][j] = 0ull;

    for (int k0 = 0; k0 < K; k0 += 32) {
#pragma unroll
        for (int i = 0; i < 4; i++) {
            int row = lrow + 32 * i;
            float4 va = *(const float4*)&A[(size_t)(m0 + row) * K + k0 + lkq * 4];
            As[lkq * 4 + 0][row] = va.x;
            As[lkq * 4 + 1][row] = va.y;
            As[lkq * 4 + 2][row] = va.z;
            As[lkq * 4 + 3][row] = va.w;
            float4 vb = *(const float4*)&B[(size_t)(n0 + row) * K + k0 + lkq * 4];
            Bs[lkq * 4 + 0][row] = vb.x;
            Bs[lkq * 4 + 1][row] = vb.y;
            Bs[lkq * 4 + 2][row] = vb.z;
            Bs[lkq * 4 + 3][row] = vb.w;
        }
        __syncthreads();

#pragma unroll
        for (int k = 0; k < 32; k++) {
            float4 a0 = *(const float4*)&As[k][ty * 8];
            float4 a1 = *(const float4*)&As[k][ty * 8 + 4];
            F4U2 b0, b1;
            b0.f = *(const float4*)&Bs[k][tx * 8];
            b1.f = *(const float4*)&Bs[k][tx * 8 + 4];
            unsigned long long bb[4] = { b0.u.x, b0.u.y, b1.u.x, b1.u.y };
            float av[8] = { a0.x, a0.y, a0.z, a0.w, a1.x, a1.y, a1.z, a1.w };
#pragma unroll
            for (int i = 0; i < 8; i++) {
                unsigned long long a2 = dup2(av[i]);
#pragma unroll
                for (int j = 0; j < 4; j++)
                    acc[i][j] = ffma2(a2, bb[j], acc[i][j]);
            }
        }
        __syncthreads();
    }

    float bv[8];
    {
        float4 t0 = *(const float4*)&bias[n0 + tx * 8];
        float4 t1 = *(const float4*)&bias[n0 + tx * 8 + 4];
        bv[0]=t0.x; bv[1]=t0.y; bv[2]=t0.z; bv[3]=t0.w;
        bv[4]=t1.x; bv[5]=t1.y; bv[6]=t1.z; bv[7]=t1.w;
    }
#pragma unroll
    for (int i = 0; i < 8; i++) {
        int row = m0 + ty * 8 + i;
        float v[8];
#pragma unroll
        for (int j = 0; j < 4; j++) unpk2(acc[i][j], v[2 * j], v[2 * j + 1]);
        float4 o0 = make_float4(v[0]+bv[0], v[1]+bv[1], v[2]+bv[2], v[3]+bv[3]);
        float4 o1 = make_float4(v[4]+bv[4], v[5]+bv[5], v[6]+bv[6], v[7]+bv[7]);
        *(float4*)&C[(size_t)row * N + n0 + tx * 8]     = o0;
        *(float4*)&C[(size_t)row * N + n0 + tx * 8 + 4] = o1;
    }
}

// ---------------------------------------------------------------------------
// Scan, barrier-free.
// ---------------------------------------------------------------------------
__device__ __forceinline__ float sigm_(float x) { return 1.0f / (1.0f + expf(-x)); }

// smem floats: h 8*1088=8704 | part 5120 | gate 256 | gxs 256 | c 64 | bias 16
#define SCAN_SMEM ((8704 + 5120 + 256 + 256 + 64 + 16) * 4)

__global__ __launch_bounds__(256, 1) void lstm_scan(
    const float* __restrict__ gx,     // [B*T, 4H]
    const float* __restrict__ w_hh,   // [4H, 512]
    const float* __restrict__ b_hh,   // [4H]
    const float* __restrict__ h0,     // [B, 512]
    const float* __restrict__ c0,     // [B, 512]
    float* __restrict__ outs,         // [B*T, 512] or nullptr
    float* __restrict__ h_final)      // [B, 512]
{
    extern __shared__ float smem[];
    float* h_all  = smem;                  // 8 warps * (16 rows * 68)
    float* part   = h_all + 8704;
    float* gate_s = part + 5120;
    float* gxs_f  = gate_s + 256;
    float* c_s    = gxs_f + 256;
    float* bias_s = c_s + 64;

    const int tid  = threadIdx.x;
    const int lane = tid & 31;
    const int wid  = tid >> 5;             // warp owns k-range [wid*64, +64)
    const int ksl  = lane >> 4;            // half-warp sub-slice
    const int r    = lane & 15;            // gate-row within CTA
    const int jb   = blockIdx.x * 4;
    const int kb   = ksl * 4;
    const int q    = lane & 15;            // producer-local index for staging
    const int bh   = lane >> 4;

    float* hw = h_all + wid * 1088;        // [b][64k], row stride 68

    const unsigned int base = *(volatile unsigned int*)&g_epoch;

    // ---- persistent: W slice into registers (16 f32x2 = 32 floats) ----
    unsigned long long w2[16];
    {
        const int grow = (r >> 2) * Hdim + jb + (r & 3);
        const float* wrow = &w_hh[(size_t)grow * Hdim + wid * 64];
#pragma unroll
        for (int kp = 0; kp < 8; kp++) {
            F4U2 t; t.f = *(const float4*)&wrow[kp * 8 + kb];
            w2[2 * kp]     = t.u.x;
            w2[2 * kp + 1] = t.u.y;
        }
    }
    if (tid < 16) bias_s[tid] = b_hh[(tid >> 2) * Hdim + jb + (tid & 3)];
    if (tid < 64) {
        int jj = tid >> 4, bb = tid & 15;
        c_s[tid] = c0[bb * Hdim + jb + jj];
    }
    // prologue: publish h0 for our 4 columns into slot 0, tag base+1
    if (tid < 16) {
        float4 v = __ldcg((const float4*)&h0[tid * Hdim + jb]);
        __stcg((float4*)&g_hbuf[0][tid * Hdim + jb], v);
    }
    __syncthreads();
    if (tid == 0) st_rel(&g_flag[0][blockIdx.x * 8], base + 1u);

    // prefetch gx for t=0
    float4 gxv = make_float4(0.f, 0.f, 0.f, 0.f);
    if (tid < 64) {
        int gg = tid >> 4, bb = tid & 15;
        gxv = __ldcg((const float4*)&gx[(size_t)(bb * Tlen) * G4H + gg * Hdim + jb]);
    }

    for (int t = 0; t < Tlen; t++) {
        // ---- acquire this step's h (per-lane RA chain with producer q) ----
        {
            const unsigned int ptag = base + (unsigned int)t + 1u;
            const unsigned int* fp = &g_flag[t & 1][(wid * 16 + q) * 8];
            unsigned int fv = ld_acq(fp);
            while ((int)(fv - ptag) < 0) fv = ld_acq(fp);
        }
        __syncwarp();
        {
            const float4* hsrc4 = (const float4*)g_hbuf[t & 1];
#pragma unroll
            for (int i = 0; i < 8; i++) {
                int b = 2 * i + bh;
                float4 v = __ldcg(&hsrc4[b * 128 + wid * 16 + q]);
                *(float4*)&hw[b * 68 + q * 4] = v;
            }
        }
        __syncwarp();

        // ---- dot: W regs x h broadcast (LDS.128) ----
        unsigned long long acc2[16];
#pragma unroll
        for (int b = 0; b < 16; b++) acc2[b] = 0ull;
#pragma unroll 2
        for (int kp = 0; kp < 8; kp++) {
#pragma unroll
            for (int b = 0; b < 16; b++) {
                F4U2 h4; h4.f = *(const float4*)&hw[b * 68 + kp * 8 + kb];
                acc2[b] = ffma2(w2[2 * kp],     h4.u.x, acc2[b]);
                acc2[b] = ffma2(w2[2 * kp + 1], h4.u.y, acc2[b]);
            }
        }

        // ---- partials: part[ks*320 + r*20 + b], ks = wid*2+ksl ----
        {
            const int ks = wid * 2 + ksl;
            float vals[16];
#pragma unroll
            for (int b = 0; b < 16; b++) {
                float lo, hi; unpk2(acc2[b], lo, hi);
                vals[b] = lo + hi;
            }
            float4* p4 = (float4*)&part[ks * 320 + r * 20];
            p4[0] = make_float4(vals[0], vals[1], vals[2], vals[3]);
            p4[1] = make_float4(vals[4], vals[5], vals[6], vals[7]);
            p4[2] = make_float4(vals[8], vals[9], vals[10], vals[11]);
            p4[3] = make_float4(vals[12], vals[13], vals[14], vals[15]);
        }
        __syncthreads();

        // ---- reduce over ks ----
        {
            int r2 = tid >> 4, b2 = tid & 15;
            float g = 0.f;
#pragma unroll
            for (int k2 = 0; k2 < 16; k2++)
                g += part[k2 * 320 + r2 * 20 + b2];
            gate_s[r2 * 16 + b2] = g;
        }
        if (tid < 64) *(float4*)&gxs_f[tid * 4] = gxv;
        __syncthreads();

        // ---- cell update + publish h (stcg), per-thread stores ----
        if (tid < 64) {
            int jj = tid >> 4, bb = tid & 15;
            float vi = gate_s[(0  + jj) * 16 + bb] + gxs_f[((0  + bb) << 2) + jj] + bias_s[jj];
            float vf = gate_s[(4  + jj) * 16 + bb] + gxs_f[((16 + bb) << 2) + jj] + bias_s[4 + jj];
            float vg = gate_s[(8  + jj) * 16 + bb] + gxs_f[((32 + bb) << 2) + jj] + bias_s[8 + jj];
            float vo = gate_s[(12 + jj) * 16 + bb] + gxs_f[((48 + bb) << 2) + jj] + bias_s[12 + jj];
            float ig = sigm_(vi);
            float fg = sigm_(vf);
            float gg = tanhf(vg);
            float og = sigm_(vo);
            float c  = fg * c_s[tid] + ig * gg;
            c_s[tid] = c;
            float h  = og * tanhf(c);
            int col = jb + jj;
            __stcg(&g_hbuf[(t + 1) & 1][bb * Hdim + col], h);
            if (outs) outs[(size_t)(bb * Tlen + t) * Hdim + col] = h;
            if (t == Tlen - 1) h_final[bb * Hdim + col] = h;
        }

        // prefetch gx for t+1 (overlaps consumer polls elsewhere)
        if (tid < 64 && t + 1 < Tlen) {
            int gg = tid >> 4, bb = tid & 15;
            gxv = __ldcg((const float4*)&gx[(size_t)(bb * Tlen + (t + 1)) * G4H + gg * Hdim + jb]);
        }

        // ---- release: one flag per CTA (orders all cell stores via bar) ----
        __syncthreads();
        if (tid == 0)
            st_rel(&g_flag[(t + 1) & 1][blockIdx.x * 8], base + (unsigned int)t + 2u);
    }

    // advance epoch for next launch / next graph replay (visible at launch boundary)
    if (blockIdx.x == 0 && tid == 0)
        *(volatile unsigned int*)&g_epoch = base + (unsigned int)Tlen + 2u;
}

// ---------------------------------------------------------------------------
extern "C" void kernel_launch(void* const* d_in, const int* in_sizes, int n_in,
                              void* d_out, int out_size)
{
    const float* x     = (const float*)d_in[0];
    const float* h0    = (const float*)d_in[1];
    const float* c0    = (const float*)d_in[2];
    const float* w_ih0 = (const float*)d_in[3];
    const float* w_hh0 = (const float*)d_in[4];
    const float* b_ih0 = (const float*)d_in[5];
    const float* b_hh0 = (const float*)d_in[6];
    const float* w_ih1 = (const float*)d_in[7];
    const float* w_hh1 = (const float*)d_in[8];
    const float* b_ih1 = (const float*)d_in[9];
    const float* b_hh1 = (const float*)d_in[10];
    float* out = (float*)d_out;

    void* p;
    cudaGetSymbolAddress(&p, g_gx);   float* gx   = (float*)p;
    cudaGetSymbolAddress(&p, g_out0); float* out0 = (float*)p;

    cudaFuncSetAttribute(lstm_scan, cudaFuncAttributeMaxDynamicSharedMemorySize,
                         SCAN_SMEM);

    const int M = Bsz * Tlen;
    dim3 ggrid(G4H / 128, M / 128);

    gemm_nt_bias<<<ggrid, 256>>>(x, w_ih0, b_ih0, gx, M, G4H, Hdim);
    lstm_scan<<<NBLK, 256, SCAN_SMEM>>>(gx, w_hh0, b_hh0,
                                        h0, c0, out0, out);
    gemm_nt_bias<<<ggrid, 256>>>(out0, w_ih1, b_ih1, gx, M, G4H, Hdim);
    lstm_scan<<<NBLK, 256, SCAN_SMEM>>>(gx, w_hh1, b_hh1,
                                        h0 + Bsz * Hdim, c0 + Bsz * Hdim,
                                        nullptr, out + Bsz * Hdim);
}

// round 7
// speedup vs baseline: 1.6169x; 1.6169x over previous
#include <cuda_runtime.h>
#include <math.h>

#define Bsz  16
#define Tlen 1024
#define Hdim 512
#define G4H  2048
#define NA   64
#define NC   64
#define NBLK (NA + NC)

__device__ float g_gx[(size_t)Bsz * Tlen * G4H];
__device__ float g_out0[(size_t)Bsz * Tlen * Hdim];
__device__ float g_h0buf[2][Bsz * Hdim];
__device__ float g_h1buf[2][Bsz * Hdim];
__device__ unsigned int g_cntA, g_cntC, g_genA, g_genC;

union F4U2 { float4 f; ulonglong2 u; };

__device__ __forceinline__ unsigned long long ffma2(unsigned long long a,
                                                    unsigned long long b,
                                                    unsigned long long c) {
    unsigned long long d;
    asm("fma.rn.f32x2 %0, %1, %2, %3;" : "=l"(d) : "l"(a), "l"(b), "l"(c));
    return d;
}
__device__ __forceinline__ unsigned long long dup2(float x) {
    unsigned long long r;
    asm("mov.b64 %0, {%1, %1};" : "=l"(r) : "f"(x));
    return r;
}
__device__ __forceinline__ void unpk2(unsigned long long v, float& lo, float& hi) {
    asm("mov.b64 {%0, %1}, %2;" : "=f"(lo), "=f"(hi) : "l"(v));
}
__device__ __forceinline__ unsigned int ld_acq(const unsigned int* p) {
    unsigned int v;
    asm volatile("ld.acquire.gpu.global.u32 %0, [%1];" : "=r"(v) : "l"(p) : "memory");
    return v;
}
__device__ __forceinline__ void st_rel(unsigned int* p, unsigned int v) {
    asm volatile("st.release.gpu.global.u32 [%0], %1;" :: "l"(p), "r"(v) : "memory");
}
__device__ __forceinline__ unsigned int atom_add_rel(unsigned int* p) {
    unsigned int old;
    asm volatile("atom.release.gpu.global.add.u32 %0, [%1], 1;"
                 : "=r"(old) : "l"(p) : "memory");
    return old;
}
__device__ __forceinline__ float sigm_(float x) {
    return __fdividef(1.0f, 1.0f + __expf(-x));
}
__device__ __forceinline__ float tanh_(float x) {
    float e = __expf(2.0f * fminf(fmaxf(x, -9.0f), 9.0f));
    return __fdividef(e - 1.0f, e + 1.0f);
}

__global__ void reset_sync() { g_cntA = 0; g_cntC = 0; g_genA = 0; g_genC = 0; }

// ---------------- GEMM (NT) for layer-0 input projection ----------------
#define GP 132
__global__ __launch_bounds__(256, 2) void gemm_nt_bias(
    const float* __restrict__ A, const float* __restrict__ B,
    const float* __restrict__ bias, float* __restrict__ C,
    int M, int N, int K)
{
    __shared__ float As[32][GP];
    __shared__ float Bs[32][GP];
    const int tid = threadIdx.x;
    const int m0 = blockIdx.y * 128, n0 = blockIdx.x * 128;
    const int tx = tid & 15, ty = tid >> 4;
    const int lrow = tid >> 3, lkq = tid & 7;

    unsigned long long acc[8][4];
#pragma unroll
    for (int i = 0; i < 8; i++)
#pragma unroll
        for (int j = 0; j < 4; j++) acc[i][j] = 0ull;

    for (int k0 = 0; k0 < K; k0 += 32) {
#pragma unroll
        for (int i = 0; i < 4; i++) {
            int row = lrow + 32 * i;
            float4 va = *(const float4*)&A[(size_t)(m0 + row) * K + k0 + lkq * 4];
            As[lkq * 4 + 0][row] = va.x; As[lkq * 4 + 1][row] = va.y;
            As[lkq * 4 + 2][row] = va.z; As[lkq * 4 + 3][row] = va.w;
            float4 vb = *(const float4*)&B[(size_t)(n0 + row) * K + k0 + lkq * 4];
            Bs[lkq * 4 + 0][row] = vb.x; Bs[lkq * 4 + 1][row] = vb.y;
            Bs[lkq * 4 + 2][row] = vb.z; Bs[lkq * 4 + 3][row] = vb.w;
        }
        __syncthreads();
#pragma unroll
        for (int k = 0; k < 32; k++) {
            float4 a0 = *(const float4*)&As[k][ty * 8];
            float4 a1 = *(const float4*)&As[k][ty * 8 + 4];
            F4U2 b0, b1;
            b0.f = *(const float4*)&Bs[k][tx * 8];
            b1.f = *(const float4*)&Bs[k][tx * 8 + 4];
            unsigned long long bb[4] = { b0.u.x, b0.u.y, b1.u.x, b1.u.y };
            float av[8] = { a0.x, a0.y, a0.z, a0.w, a1.x, a1.y, a1.z, a1.w };
#pragma unroll
            for (int i = 0; i < 8; i++) {
                unsigned long long a2 = dup2(av[i]);
#pragma unroll
                for (int j = 0; j < 4; j++) acc[i][j] = ffma2(a2, bb[j], acc[i][j]);
            }
        }
        __syncthreads();
    }
    float bv[8];
    {
        float4 t0 = *(const float4*)&bias[n0 + tx * 8];
        float4 t1 = *(const float4*)&bias[n0 + tx * 8 + 4];
        bv[0]=t0.x; bv[1]=t0.y; bv[2]=t0.z; bv[3]=t0.w;
        bv[4]=t1.x; bv[5]=t1.y; bv[6]=t1.z; bv[7]=t1.w;
    }
#pragma unroll
    for (int i = 0; i < 8; i++) {
        int row = m0 + ty * 8 + i;
        float v[8];
#pragma unroll
        for (int j = 0; j < 4; j++) unpk2(acc[i][j], v[2 * j], v[2 * j + 1]);
        *(float4*)&C[(size_t)row * N + n0 + tx * 8] =
            make_float4(v[0]+bv[0], v[1]+bv[1], v[2]+bv[2], v[3]+bv[3]);
        *(float4*)&C[(size_t)row * N + n0 + tx * 8 + 4] =
            make_float4(v[4]+bv[4], v[5]+bv[5], v[6]+bv[6], v[7]+bv[7]);
    }
}

// ---------------- Fused dual-layer pipelined scan ----------------
// smem floats (C layout, max): wih 16384 | h 8704 | o 8704 | part 10368 |
//                              gate 512 | gxs 576 | c 128 | bias 32
#define SCAN_SMEM ((16384 + 8704 + 8704 + 10368 + 512 + 576 + 128 + 32) * 4)

__global__ __launch_bounds__(256, 1) void lstm_fused(
    const float* __restrict__ gx,
    const float* __restrict__ w_hh0, const float* __restrict__ b_hh0,
    const float* __restrict__ w_ih1, const float* __restrict__ w_hh1,
    const float* __restrict__ b_ih1, const float* __restrict__ b_hh1,
    const float* __restrict__ h0, const float* __restrict__ c0,
    float* __restrict__ out)
{
    extern __shared__ float smem[];
    const int tid = threadIdx.x, lane = tid & 31;
    const int kwid = tid >> 5, ksl = lane >> 4, rslot = lane & 15;
    const bool isA = (blockIdx.x < NA);
    const int jb = (isA ? blockIdx.x : blockIdx.x - NA) * 8;

    float* wih_s  = smem;                          // C only
    float* h_all  = isA ? smem : wih_s + 16384;
    float* o_all  = h_all + 8704;                  // C only
    float* part   = (isA ? h_all : o_all) + 8704;
    float* gate_s = part + 10368;
    float* gxs    = gate_s + 512;                  // A only
    float* c_s    = gxs + 576;
    float* bias_s = c_s + 128;
    float* hw = h_all + kwid * 1088;               // [16 b][64 k] pitch 68
    float* ow = o_all + kwid * 1088;

    // W_hh slice into registers: rows rslot, rslot+16
    const float* whh = isA ? w_hh0 : w_hh1;
    unsigned long long w0[16], w1[16];
    {
        const int g0 = (rslot >> 3) * Hdim + jb + (rslot & 7);
        const int g1 = ((rslot + 16) >> 3) * Hdim + jb + ((rslot + 16) & 7);
        const float* p0 = &whh[(size_t)g0 * Hdim + kwid * 64 + ksl * 32];
        const float* p1 = &whh[(size_t)g1 * Hdim + kwid * 64 + ksl * 32];
#pragma unroll
        for (int kp = 0; kp < 8; kp++) {
            F4U2 a; a.f = *(const float4*)&p0[kp * 4];
            w0[2 * kp] = a.u.x; w0[2 * kp + 1] = a.u.y;
            F4U2 b; b.f = *(const float4*)&p1[kp * 4];
            w1[2 * kp] = b.u.x; w1[2 * kp + 1] = b.u.y;
        }
    }
    if (!isA) {  // W_ih1 slice into smem: [(kq*32+row)*4]
#pragma unroll
        for (int i = 0; i < 16; i++) {
            int idx = tid + 256 * i, kq = idx >> 5, row = idx & 31;
            int grow = (row >> 3) * Hdim + jb + (row & 7);
            *(float4*)&wih_s[(size_t)(kq * 32 + row) * 4] =
                *(const float4*)&w_ih1[(size_t)grow * Hdim + kq * 4];
        }
    }
    if (tid < 32) {
        int grow = (tid >> 3) * Hdim + jb + (tid & 7);
        bias_s[tid] = isA ? b_hh0[grow] : (b_ih1[grow] + b_hh1[grow]);
    }
    if (tid < 128) {
        int jj = tid >> 4, b = tid & 15;
        c_s[tid] = c0[(isA ? 0 : Bsz * Hdim) + b * Hdim + jb + jj];
    }
    __syncthreads();

    float4 gxv = make_float4(0.f, 0.f, 0.f, 0.f);
    if (isA && tid < 128) {
        int b = tid >> 3, g = (tid >> 1) & 3, hf = tid & 1;
        gxv = __ldcg((const float4*)&gx[(size_t)(b * Tlen) * G4H + g * Hdim + jb + hf * 4]);
    }

    for (int t = 0; t < Tlen; t++) {
        // top-of-step waits (1 poller)
        if (tid == 0) {
            if (isA) {
                if (t > 0) while (ld_acq(&g_genA) < (unsigned)t) { }
            } else {
                if (t > 0) while (ld_acq(&g_genC) < (unsigned)t) { }
                while (ld_acq(&g_genA) < (unsigned)(t + 1)) { }
            }
        }
        __syncthreads();

        // stage h (and out0 for C), own 64-k slice per warp
        const float* hsrc = isA
            ? ((t == 0) ? h0 : g_h0buf[t & 1])
            : ((t == 0) ? h0 + Bsz * Hdim : g_h1buf[t & 1]);
#pragma unroll
        for (int i = 0; i < 8; i++) {
            int idx = lane + 32 * i, b = idx >> 4, q = idx & 15;
            float4 v = __ldcg((const float4*)&hsrc[b * Hdim + kwid * 64 + q * 4]);
            *(float4*)&hw[b * 68 + q * 4] = v;
            if (!isA) {
                float4 o = __ldcg((const float4*)&g_out0[(size_t)(b * Tlen + t) * Hdim + kwid * 64 + q * 4]);
                *(float4*)&ow[b * 68 + q * 4] = o;
            }
        }
        __syncwarp();

        // dot: rows rslot, rslot+16
        unsigned long long acc0[16], acc1[16];
#pragma unroll
        for (int b = 0; b < 16; b++) { acc0[b] = 0ull; acc1[b] = 0ull; }
#pragma unroll
        for (int kp = 0; kp < 8; kp++) {
#pragma unroll
            for (int b = 0; b < 16; b++) {
                F4U2 h4; h4.f = *(const float4*)&hw[b * 68 + ksl * 32 + kp * 4];
                acc0[b] = ffma2(w0[2 * kp],     h4.u.x, acc0[b]);
                acc0[b] = ffma2(w0[2 * kp + 1], h4.u.y, acc0[b]);
                acc1[b] = ffma2(w1[2 * kp],     h4.u.x, acc1[b]);
                acc1[b] = ffma2(w1[2 * kp + 1], h4.u.y, acc1[b]);
            }
        }
        if (!isA) {
#pragma unroll
            for (int kp = 0; kp < 8; kp++) {
                const int kq = kwid * 16 + ksl * 8 + kp;
                F4U2 wa; wa.f = *(const float4*)&wih_s[(size_t)(kq * 32 + rslot) * 4];
                F4U2 wb; wb.f = *(const float4*)&wih_s[(size_t)(kq * 32 + rslot + 16) * 4];
#pragma unroll
                for (int b = 0; b < 16; b++) {
                    F4U2 o4; o4.f = *(const float4*)&ow[b * 68 + ksl * 32 + kp * 4];
                    acc0[b] = ffma2(wa.u.x, o4.u.x, acc0[b]);
                    acc0[b] = ffma2(wa.u.y, o4.u.y, acc0[b]);
                    acc1[b] = ffma2(wb.u.x, o4.u.x, acc1[b]);
                    acc1[b] = ffma2(wb.u.y, o4.u.y, acc1[b]);
                }
            }
        }
        // partials: part[ks*648 + row*20 + b]
        {
            const int ks = kwid * 2 + ksl;
            float v0[16], v1[16];
#pragma unroll
            for (int b = 0; b < 16; b++) {
                float lo, hi;
                unpk2(acc0[b], lo, hi); v0[b] = lo + hi;
                unpk2(acc1[b], lo, hi); v1[b] = lo + hi;
            }
            float4* p0 = (float4*)&part[ks * 648 + rslot * 20];
            float4* p1 = (float4*)&part[ks * 648 + (rslot + 16) * 20];
#pragma unroll
            for (int j = 0; j < 4; j++) {
                p0[j] = make_float4(v0[4*j], v0[4*j+1], v0[4*j+2], v0[4*j+3]);
                p1[j] = make_float4(v1[4*j], v1[4*j+1], v1[4*j+2], v1[4*j+3]);
            }
        }
        if (isA && tid < 128) {
            int b = tid >> 3, g = (tid >> 1) & 3, hf = tid & 1;
            *(float4*)&gxs[b * 36 + g * 8 + hf * 4] = gxv;
        }
        __syncthreads();

        // reduce over 16 k-slices (rows rr, rr+16)
        {
            int rr = tid >> 4, b2 = tid & 15;
            float gA = 0.f, gB = 0.f;
#pragma unroll
            for (int k2 = 0; k2 < 16; k2++) {
                gA += part[k2 * 648 + rr * 20 + b2];
                gB += part[k2 * 648 + (rr + 16) * 20 + b2];
            }
            gate_s[rr * 16 + b2] = gA;
            gate_s[(rr + 16) * 16 + b2] = gB;
        }
        __syncthreads();

        // cell (8 cols x 16 b)
        if (tid < 128) {
            int jj = tid >> 4, b = tid & 15;
            float vi = gate_s[(0  + jj) * 16 + b] + bias_s[jj];
            float vf = gate_s[(8  + jj) * 16 + b] + bias_s[8 + jj];
            float vg = gate_s[(16 + jj) * 16 + b] + bias_s[16 + jj];
            float vo = gate_s[(24 + jj) * 16 + b] + bias_s[24 + jj];
            if (isA) {
                vi += gxs[b * 36 + jj];       vf += gxs[b * 36 + 8 + jj];
                vg += gxs[b * 36 + 16 + jj];  vo += gxs[b * 36 + 24 + jj];
            }
            float ig = sigm_(vi), fg = sigm_(vf);
            float gg = tanh_(vg), og = sigm_(vo);
            float c = fg * c_s[tid] + ig * gg;
            c_s[tid] = c;
            float h = og * tanh_(c);
            int col = jb + jj;
            if (isA) {
                __stcg(&g_h0buf[(t + 1) & 1][b * Hdim + col], h);
                __stcg(&g_out0[(size_t)(b * Tlen + t) * Hdim + col], h);
                if (t == Tlen - 1) out[b * Hdim + col] = h;
            } else {
                __stcg(&g_h1buf[(t + 1) & 1][b * Hdim + col], h);
                if (t == Tlen - 1) out[Bsz * Hdim + b * Hdim + col] = h;
            }
        }
        if (isA && tid < 128 && t + 1 < Tlen) {
            int b = tid >> 3, g = (tid >> 1) & 3, hf = tid & 1;
            gxv = __ldcg((const float4*)&gx[(size_t)(b * Tlen + t + 1) * G4H + g * Hdim + jb + hf * 4]);
        }
        __syncthreads();

        // arrival (A always — C needs genA=Tlen; C skips last)
        if (tid == 0) {
            if (isA) {
                unsigned int old = atom_add_rel(&g_cntA);
                if (old == (unsigned)NA * (t + 1) - 1u)
                    st_rel(&g_genA, (unsigned)(t + 1));
            } else if (t < Tlen - 1) {
                unsigned int old = atom_add_rel(&g_cntC);
                if (old == (unsigned)NC * (t + 1) - 1u)
                    st_rel(&g_genC, (unsigned)(t + 1));
            }
        }
    }
}

// ---------------------------------------------------------------------------
extern "C" void kernel_launch(void* const* d_in, const int* in_sizes, int n_in,
                              void* d_out, int out_size)
{
    const float* x     = (const float*)d_in[0];
    const float* h0    = (const float*)d_in[1];
    const float* c0    = (const float*)d_in[2];
    const float* w_ih0 = (const float*)d_in[3];
    const float* w_hh0 = (const float*)d_in[4];
    const float* b_ih0 = (const float*)d_in[5];
    const float* b_hh0 = (const float*)d_in[6];
    const float* w_ih1 = (const float*)d_in[7];
    const float* w_hh1 = (const float*)d_in[8];
    const float* b_ih1 = (const float*)d_in[9];
    const float* b_hh1 = (const float*)d_in[10];
    float* out = (float*)d_out;

    void* p;
    cudaGetSymbolAddress(&p, g_gx);
    float* gx = (float*)p;

    cudaFuncSetAttribute(lstm_fused, cudaFuncAttributeMaxDynamicSharedMemorySize,
                         SCAN_SMEM);

    reset_sync<<<1, 1>>>();
    const int M = Bsz * Tlen;
    dim3 ggrid(G4H / 128, M / 128);
    gemm_nt_bias<<<ggrid, 256>>>(x, w_ih0, b_ih0, gx, M, G4H, Hdim);
    lstm_fused<<<NBLK, 256, SCAN_SMEM>>>(gx, w_hh0, b_hh0,
                                         w_ih1, w_hh1, b_ih1, b_hh1,
                                         h0, c0, out);
}

// round 8
// speedup vs baseline: 1.9861x; 1.2284x over previous
#include <cuda_runtime.h>
#include <math.h>

#define Bsz  16
#define Tlen 1024
#define Hdim 512
#define G4H  2048
#define NA   64
#define NC   64
#define NBLK (NA + NC)

__device__ float g_gx[(size_t)Bsz * Tlen * G4H];
__device__ float g_out0[(size_t)Bsz * Tlen * Hdim];
__device__ float g_h0buf[2][Bsz * Hdim];
__device__ float g_h1buf[2][Bsz * Hdim];
__device__ unsigned int g_leafA[8 * 64], g_leafC[8 * 64];  // 256B-strided leaves
__device__ unsigned int g_topA, g_topC;

union F4U2 { float4 f; ulonglong2 u; };

__device__ __forceinline__ unsigned long long ffma2(unsigned long long a,
                                                    unsigned long long b,
                                                    unsigned long long c) {
    unsigned long long d;
    asm("fma.rn.f32x2 %0, %1, %2, %3;" : "=l"(d) : "l"(a), "l"(b), "l"(c));
    return d;
}
__device__ __forceinline__ unsigned long long dup2(float x) {
    unsigned long long r;
    asm("mov.b64 %0, {%1, %1};" : "=l"(r) : "f"(x));
    return r;
}
__device__ __forceinline__ void unpk2(unsigned long long v, float& lo, float& hi) {
    asm("mov.b64 {%0, %1}, %2;" : "=f"(lo), "=f"(hi) : "l"(v));
}
__device__ __forceinline__ unsigned int ld_acq(const unsigned int* p) {
    unsigned int v;
    asm volatile("ld.acquire.gpu.global.u32 %0, [%1];" : "=r"(v) : "l"(p) : "memory");
    return v;
}
__device__ __forceinline__ void arrive_tree(unsigned int* leaf, unsigned int* top,
                                            unsigned int target8) {
    unsigned int old;
    asm volatile("atom.acq_rel.gpu.global.add.u32 %0, [%1], 1;"
                 : "=r"(old) : "l"(leaf) : "memory");
    if (old == target8 - 1u)
        asm volatile("red.release.gpu.global.add.u32 [%0], 1;" :: "l"(top) : "memory");
}
__device__ __forceinline__ float sigm_(float x) {
    return __fdividef(1.0f, 1.0f + __expf(-x));
}
__device__ __forceinline__ float tanh_(float x) {
    float e = __expf(2.0f * fminf(fmaxf(x, -9.0f), 9.0f));
    return __fdividef(e - 1.0f, e + 1.0f);
}

// ---------------- GEMM (NT) + sync reset ----------------
#define GP 132
__global__ __launch_bounds__(256, 2) void gemm_nt_bias(
    const float* __restrict__ A, const float* __restrict__ B,
    const float* __restrict__ bias, float* __restrict__ C,
    int M, int N, int K)
{
    if (blockIdx.x == 0 && blockIdx.y == 0 && threadIdx.x < 8) {
        g_leafA[threadIdx.x * 64] = 0u;
        g_leafC[threadIdx.x * 64] = 0u;
        if (threadIdx.x == 0) { g_topA = 0u; g_topC = 0u; }
    }
    __shared__ float As[32][GP];
    __shared__ float Bs[32][GP];
    const int tid = threadIdx.x;
    const int m0 = blockIdx.y * 128, n0 = blockIdx.x * 128;
    const int tx = tid & 15, ty = tid >> 4;
    const int lrow = tid >> 3, lkq = tid & 7;

    unsigned long long acc[8][4];
#pragma unroll
    for (int i = 0; i < 8; i++)
#pragma unroll
        for (int j = 0; j < 4; j++) acc[i][j] = 0ull;

    for (int k0 = 0; k0 < K; k0 += 32) {
#pragma unroll
        for (int i = 0; i < 4; i++) {
            int row = lrow + 32 * i;
            float4 va = *(const float4*)&A[(size_t)(m0 + row) * K + k0 + lkq * 4];
            As[lkq * 4 + 0][row] = va.x; As[lkq * 4 + 1][row] = va.y;
            As[lkq * 4 + 2][row] = va.z; As[lkq * 4 + 3][row] = va.w;
            float4 vb = *(const float4*)&B[(size_t)(n0 + row) * K + k0 + lkq * 4];
            Bs[lkq * 4 + 0][row] = vb.x; Bs[lkq * 4 + 1][row] = vb.y;
            Bs[lkq * 4 + 2][row] = vb.z; Bs[lkq * 4 + 3][row] = vb.w;
        }
        __syncthreads();
#pragma unroll
        for (int k = 0; k < 32; k++) {
            float4 a0 = *(const float4*)&As[k][ty * 8];
            float4 a1 = *(const float4*)&As[k][ty * 8 + 4];
            F4U2 b0, b1;
            b0.f = *(const float4*)&Bs[k][tx * 8];
            b1.f = *(const float4*)&Bs[k][tx * 8 + 4];
            unsigned long long bb[4] = { b0.u.x, b0.u.y, b1.u.x, b1.u.y };
            float av[8] = { a0.x, a0.y, a0.z, a0.w, a1.x, a1.y, a1.z, a1.w };
#pragma unroll
            for (int i = 0; i < 8; i++) {
                unsigned long long a2 = dup2(av[i]);
#pragma unroll
                for (int j = 0; j < 4; j++) acc[i][j] = ffma2(a2, bb[j], acc[i][j]);
            }
        }
        __syncthreads();
    }
    float bv[8];
    {
        float4 t0 = *(const float4*)&bias[n0 + tx * 8];
        float4 t1 = *(const float4*)&bias[n0 + tx * 8 + 4];
        bv[0]=t0.x; bv[1]=t0.y; bv[2]=t0.z; bv[3]=t0.w;
        bv[4]=t1.x; bv[5]=t1.y; bv[6]=t1.z; bv[7]=t1.w;
    }
#pragma unroll
    for (int i = 0; i < 8; i++) {
        int row = m0 + ty * 8 + i;
        float v[8];
#pragma unroll
        for (int j = 0; j < 4; j++) unpk2(acc[i][j], v[2 * j], v[2 * j + 1]);
        *(float4*)&C[(size_t)row * N + n0 + tx * 8] =
            make_float4(v[0]+bv[0], v[1]+bv[1], v[2]+bv[2], v[3]+bv[3]);
        *(float4*)&C[(size_t)row * N + n0 + tx * 8 + 4] =
            make_float4(v[4]+bv[4], v[5]+bv[5], v[6]+bv[6], v[7]+bv[7]);
    }
}

// ---------------- Fused dual-layer pipelined scan ----------------
// smem floats (C max): wih 16384 | h 8704 | o 8704 | part 10368 | gxs 576 | c 128 | bias 32
#define SCAN_SMEM ((16384 + 8704 + 8704 + 10368 + 576 + 128 + 32) * 4)

__global__ __launch_bounds__(256, 1) void lstm_fused(
    const float* __restrict__ gx,
    const float* __restrict__ w_hh0, const float* __restrict__ b_hh0,
    const float* __restrict__ w_ih1, const float* __restrict__ w_hh1,
    const float* __restrict__ b_ih1, const float* __restrict__ b_hh1,
    const float* __restrict__ h0, const float* __restrict__ c0,
    float* __restrict__ out)
{
    extern __shared__ float smem[];
    const int tid = threadIdx.x, lane = tid & 31;
    const int kwid = tid >> 5, ksl = lane >> 4, rslot = lane & 15;
    const bool isA = (blockIdx.x < NA);
    const int gbid = isA ? blockIdx.x : blockIdx.x - NA;
    const int jb = gbid * 8;
    unsigned int* myLeaf = (isA ? g_leafA : g_leafC) + (gbid & 7) * 64;
    unsigned int* myTop  = isA ? &g_topA : &g_topC;

    float* wih_s  = smem;
    float* h_all  = isA ? smem : wih_s + 16384;
    float* o_all  = h_all + 8704;
    float* part   = (isA ? h_all : o_all) + 8704;
    float* gxs    = part + 10368;
    float* c_s    = gxs + 576;
    float* bias_s = c_s + 128;
    float* hw = h_all + kwid * 1088;   // [16 b][64 k] pitch 68
    float* ow = o_all + kwid * 1088;

    const float* whh = isA ? w_hh0 : w_hh1;
    unsigned long long w0[16], w1[16];
    {
        const int g0 = (rslot >> 3) * Hdim + jb + (rslot & 7);
        const int g1 = ((rslot + 16) >> 3) * Hdim + jb + ((rslot + 16) & 7);
        const float* p0 = &whh[(size_t)g0 * Hdim + kwid * 64 + ksl * 32];
        const float* p1 = &whh[(size_t)g1 * Hdim + kwid * 64 + ksl * 32];
#pragma unroll
        for (int kp = 0; kp < 8; kp++) {
            F4U2 a; a.f = *(const float4*)&p0[kp * 4];
            w0[2 * kp] = a.u.x; w0[2 * kp + 1] = a.u.y;
            F4U2 b; b.f = *(const float4*)&p1[kp * 4];
            w1[2 * kp] = b.u.x; w1[2 * kp + 1] = b.u.y;
        }
    }
    if (!isA) {
#pragma unroll
        for (int i = 0; i < 16; i++) {
            int idx = tid + 256 * i, kq = idx >> 5, row = idx & 31;
            int grow = (row >> 3) * Hdim + jb + (row & 7);
            *(float4*)&wih_s[(size_t)(kq * 32 + row) * 4] =
                *(const float4*)&w_ih1[(size_t)grow * Hdim + kq * 4];
        }
    }
    if (tid < 32) {
        int grow = (tid >> 3) * Hdim + jb + (tid & 7);
        bias_s[tid] = isA ? b_hh0[grow] : (b_ih1[grow] + b_hh1[grow]);
    }
    if (tid < 128) {
        int jj = tid >> 4, b = tid & 15;
        c_s[tid] = c0[(isA ? 0 : Bsz * Hdim) + b * Hdim + jb + jj];
    }
    __syncthreads();

    float4 gxv = make_float4(0.f, 0.f, 0.f, 0.f);
    if (isA && tid < 128) {
        int b = tid >> 3, g = (tid >> 1) & 3, hf = tid & 1;
        gxv = __ldcg((const float4*)&gx[(size_t)(b * Tlen) * G4H + g * Hdim + jb + hf * 4]);
    }
    if (!isA) {  // prologue: stage ow(0) once A finishes step 0
        if (lane == 0) while (ld_acq(&g_topA) < 8u) { }
        __syncwarp();
#pragma unroll
        for (int i = 0; i < 8; i++) {
            int idx = lane + 32 * i, b = idx >> 4, q = idx & 15;
            float4 o = __ldcg((const float4*)&g_out0[(size_t)(b * Tlen) * Hdim + kwid * 64 + q * 4]);
            *(float4*)&ow[b * 68 + q * 4] = o;
        }
        __syncwarp();
    }

    for (int t = 0; t < Tlen; t++) {
        unsigned long long acc0[16], acc1[16];
#pragma unroll
        for (int b = 0; b < 16; b++) { acc0[b] = 0ull; acc1[b] = 0ull; }

        if (!isA) {  // ih dot FIRST — hides own-group barrier latency
#pragma unroll
            for (int kp = 0; kp < 8; kp++) {
                const int kq = kwid * 16 + ksl * 8 + kp;
                F4U2 wa; wa.f = *(const float4*)&wih_s[(size_t)(kq * 32 + rslot) * 4];
                F4U2 wb; wb.f = *(const float4*)&wih_s[(size_t)(kq * 32 + rslot + 16) * 4];
#pragma unroll
                for (int b = 0; b < 16; b++) {
                    F4U2 o4; o4.f = *(const float4*)&ow[b * 68 + ksl * 32 + kp * 4];
                    acc0[b] = ffma2(wa.u.x, o4.u.x, acc0[b]);
                    acc0[b] = ffma2(wa.u.y, o4.u.y, acc0[b]);
                    acc1[b] = ffma2(wb.u.x, o4.u.x, acc1[b]);
                    acc1[b] = ffma2(wb.u.y, o4.u.y, acc1[b]);
                }
            }
        }

        // per-warp gate + stage h
        if (lane == 0 && t > 0) {
            while (ld_acq(myTop) < 8u * (unsigned)t) { }
        }
        __syncwarp();
        const float* hsrc = isA
            ? ((t == 0) ? h0 : g_h0buf[t & 1])
            : ((t == 0) ? h0 + Bsz * Hdim : g_h1buf[t & 1]);
#pragma unroll
        for (int i = 0; i < 8; i++) {
            int idx = lane + 32 * i, b = idx >> 4, q = idx & 15;
            float4 v = __ldcg((const float4*)&hsrc[b * Hdim + kwid * 64 + q * 4]);
            *(float4*)&hw[b * 68 + q * 4] = v;
        }
        __syncwarp();

        // hh dot
#pragma unroll
        for (int kp = 0; kp < 8; kp++) {
#pragma unroll
            for (int b = 0; b < 16; b++) {
                F4U2 h4; h4.f = *(const float4*)&hw[b * 68 + ksl * 32 + kp * 4];
                acc0[b] = ffma2(w0[2 * kp],     h4.u.x, acc0[b]);
                acc0[b] = ffma2(w0[2 * kp + 1], h4.u.y, acc0[b]);
                acc1[b] = ffma2(w1[2 * kp],     h4.u.x, acc1[b]);
                acc1[b] = ffma2(w1[2 * kp + 1], h4.u.y, acc1[b]);
            }
        }
        // partials
        {
            const int ks = kwid * 2 + ksl;
            float v0[16], v1[16];
#pragma unroll
            for (int b = 0; b < 16; b++) {
                float lo, hi;
                unpk2(acc0[b], lo, hi); v0[b] = lo + hi;
                unpk2(acc1[b], lo, hi); v1[b] = lo + hi;
            }
            float4* p0 = (float4*)&part[ks * 648 + rslot * 20];
            float4* p1 = (float4*)&part[ks * 648 + (rslot + 16) * 20];
#pragma unroll
            for (int j = 0; j < 4; j++) {
                p0[j] = make_float4(v0[4*j], v0[4*j+1], v0[4*j+2], v0[4*j+3]);
                p1[j] = make_float4(v1[4*j], v1[4*j+1], v1[4*j+2], v1[4*j+3]);
            }
        }
        if (isA && tid < 128) {
            int b = tid >> 3, g = (tid >> 1) & 3, hf = tid & 1;
            *(float4*)&gxs[b * 36 + g * 8 + hf * 4] = gxv;
        }
        __syncthreads();

        // cell (warps 0-3): reduce folded in
        if (tid < 128) {
            int jj = tid >> 4, b = tid & 15;
            float vi = 0.f, vf = 0.f, vg = 0.f, vo = 0.f;
#pragma unroll
            for (int k2 = 0; k2 < 16; k2++) {
                const float* pk = &part[k2 * 648 + b];
                vi += pk[(0  + jj) * 20];
                vf += pk[(8  + jj) * 20];
                vg += pk[(16 + jj) * 20];
                vo += pk[(24 + jj) * 20];
            }
            vi += bias_s[jj];      vf += bias_s[8 + jj];
            vg += bias_s[16 + jj]; vo += bias_s[24 + jj];
            if (isA) {
                vi += gxs[b * 36 + jj];       vf += gxs[b * 36 + 8 + jj];
                vg += gxs[b * 36 + 16 + jj];  vo += gxs[b * 36 + 24 + jj];
            }
            float ig = sigm_(vi), fg = sigm_(vf);
            float gg = tanh_(vg), og = sigm_(vo);
            float c = fg * c_s[tid] + ig * gg;
            c_s[tid] = c;
            float h = og * tanh_(c);
            int col = jb + jj;
            if (isA) {
                __stcg(&g_h0buf[(t + 1) & 1][b * Hdim + col], h);
                __stcg(&g_out0[(size_t)(b * Tlen + t) * Hdim + col], h);
                if (t == Tlen - 1) out[b * Hdim + col] = h;
            } else {
                __stcg(&g_h1buf[(t + 1) & 1][b * Hdim + col], h);
                if (t == Tlen - 1) out[Bsz * Hdim + b * Hdim + col] = h;
            }
        }
        // overlapped next-step prefetches
        if (isA) {
            if (tid < 128 && t + 1 < Tlen) {
                int b = tid >> 3, g = (tid >> 1) & 3, hf = tid & 1;
                gxv = __ldcg((const float4*)&gx[(size_t)(b * Tlen + t + 1) * G4H + g * Hdim + jb + hf * 4]);
            }
        } else if (t + 1 < Tlen) {
            if (lane == 0) while (ld_acq(&g_topA) < 8u * (unsigned)(t + 2)) { }
            __syncwarp();
#pragma unroll
            for (int i = 0; i < 8; i++) {
                int idx = lane + 32 * i, b = idx >> 4, q = idx & 15;
                float4 o = __ldcg((const float4*)&g_out0[(size_t)(b * Tlen + t + 1) * Hdim + kwid * 64 + q * 4]);
                *(float4*)&ow[b * 68 + q * 4] = o;
            }
        }
        __syncthreads();

        if (tid == 0 && (isA || t < Tlen - 1))
            arrive_tree(myLeaf, myTop, 8u * (unsigned)(t + 1));
    }
}

// ---------------------------------------------------------------------------
extern "C" void kernel_launch(void* const* d_in, const int* in_sizes, int n_in,
                              void* d_out, int out_size)
{
    const float* x     = (const float*)d_in[0];
    const float* h0    = (const float*)d_in[1];
    const float* c0    = (const float*)d_in[2];
    const float* w_ih0 = (const float*)d_in[3];
    const float* w_hh0 = (const float*)d_in[4];
    const float* b_ih0 = (const float*)d_in[5];
    const float* b_hh0 = (const float*)d_in[6];
    const float* w_ih1 = (const float*)d_in[7];
    const float* w_hh1 = (const float*)d_in[8];
    const float* b_ih1 = (const float*)d_in[9];
    const float* b_hh1 = (const float*)d_in[10];
    float* out = (float*)d_out;

    void* p;
    cudaGetSymbolAddress(&p, g_gx);
    float* gx = (float*)p;

    cudaFuncSetAttribute(lstm_fused, cudaFuncAttributeMaxDynamicSharedMemorySize,
                         SCAN_SMEM);

    const int M = Bsz * Tlen;
    dim3 ggrid(G4H / 128, M / 128);
    gemm_nt_bias<<<ggrid, 256>>>(x, w_ih0, b_ih0, gx, M, G4H, Hdim);
    lstm_fused<<<NBLK, 256, SCAN_SMEM>>>(gx, w_hh0, b_hh0,
                                         w_ih1, w_hh1, b_ih1, b_hh1,
                                         h0, c0, out);
}